// round 6
// baseline (speedup 1.0000x reference)
#include <cuda_runtime.h>

// cost_volumn: out[n,y,x, i*9+j] = (1/128) * sum_c f1[n,y,x,c] * f2[n, y+i-4, x+j-4, c]
// f1,f2: [8,128,256,128] f32 NHWC; out: [8,128,256,81] f32. Zero padding outside.
//
// Pipeline per chunk of CC=4 channels:
//   cp.async (issued 1 iter ahead) -> raw pixel-major smem (double buffered)
//   own-item smem transpose        -> swizzled channel-major window buffer (double buffered)
//   register-window FMA compute (72 acc/thread)
// One __syncthreads per chunk; DRAM traffic fully overlapped with compute.

#define DN 8
#define DH 128
#define DW 256
#define DC 128
#define RAD 4
#define NDX 9
#define NOFF 81

constexpr int YB      = 2;             // output rows per block
constexpr int CC      = 4;             // channels per chunk (= one float4 per pixel)
constexpr int NCH     = DC / CC;       // 32 chunks
constexpr int PX      = 8;             // pixels per thread
constexpr int THREADS = 576;           // 18 warps; warp=(row,dy), lane=x-group
constexpr int XCOLS   = DW + 2 * RAD;  // 264
constexpr int YROWS   = YB + 2 * RAD;  // 10 f2 rows per block
constexpr int ROWLEN  = 276;           // padded transposed-row stride (floats)

constexpr int F2ITEMS  = YROWS * XCOLS;       // 2640 float4 items per chunk
constexpr int TOTITEMS = F2ITEMS + YB * DW;   // 3152 (f2 + f1)
constexpr int TROWS    = (YROWS + YB) * CC;   // 48 transposed rows
constexpr int RAWF     = TOTITEMS * 4;        // floats per raw buffer
constexpr int TF       = TROWS * ROWLEN;      // floats per transposed buffer
constexpr int SMEM_BYTES = (2 * RAWF + 2 * TF) * 4;   // 206,848 B

// XOR swizzle on 16B chunks: conflict-free window LDS.128 + transpose STS.
__device__ __forceinline__ int swzidx(int xc) {
    int j = xc >> 2;
    j ^= (j >> 3) & 7;
    return (j << 2) | (xc & 3);
}
__device__ __forceinline__ int swzchunk4(int j) {
    return (j ^ ((j >> 3) & 7)) << 2;
}

extern __shared__ float smem[];

__device__ __forceinline__ void cp16(unsigned dst, const void* src, int srcsize) {
    asm volatile("cp.async.cg.shared.global [%0], [%1], 16, %2;\n"
                 :: "r"(dst), "l"(src), "r"(srcsize));
}

__global__ __launch_bounds__(THREADS, 1)
void costvol_kernel(const float* __restrict__ f1,
                    const float* __restrict__ f2,
                    float* __restrict__ out)
{
    const int y0  = blockIdx.x * YB;
    const int n   = blockIdx.y;
    const int tid = threadIdx.x;
    const int w   = tid >> 5;
    const int r   = w / NDX;           // output row in block (0..1)
    const int i   = w % NDX;           // dy 0..8
    const int g   = tid & 31;          // x-group: pixels 8g..8g+7

    float* rawA = smem;                 // raw chunk buffers (pixel-major, linear)
    float* rawB = smem + RAWF;
    float* tbuf[2] = { smem + 2 * RAWF, smem + 2 * RAWF + TF };
    float* rawbuf[2] = { rawA, rawB };

    const unsigned rawA_u = (unsigned)__cvta_generic_to_shared(rawA);
    const unsigned rawB_u = (unsigned)__cvta_generic_to_shared(rawB);
    const unsigned raw_u[2] = { rawA_u, rawB_u };

    const int rowPix = (n * DH + y0) * DW;

    // ---- cp.async issue of one chunk's raw data (pixel-major, zero-filled pad) ----
    auto issue_chunk = [&](int ch, unsigned rbase) {
        const int cofs = ch * CC;
        for (int t = tid; t < TOTITEMS; t += THREADS) {
            const float* src;
            int sz;
            if (t < F2ITEMS) {
                const int xcol = t % XCOLS;
                const int row  = t / XCOLS;
                const int y2 = y0 + row - RAD;
                const int x2 = xcol - RAD;
                const bool ok = ((unsigned)y2 < DH) & ((unsigned)x2 < DW);
                const int yc = ok ? y2 : 0;
                const int xc = ok ? x2 : 0;
                src = f2 + (size_t)((n * DH + yc) * DW + xc) * DC + cofs;
                sz  = ok ? 16 : 0;
            } else {
                const int u  = t - F2ITEMS;
                const int x  = u & (DW - 1);
                const int r2 = u >> 8;
                src = f1 + (size_t)(rowPix + r2 * DW + x) * DC + cofs;
                sz  = 16;
            }
            cp16(rbase + (unsigned)t * 16u, src, sz);
        }
        asm volatile("cp.async.commit_group;\n" ::: "memory");
    };

    // ---- transpose own raw items -> swizzled channel-major buffer ----
    auto transpose_chunk = [&](const float* rbuf, float* tb) {
        float* tF1 = tb + YROWS * CC * ROWLEN;
        for (int t = tid; t < TOTITEMS; t += THREADS) {
            const float4 v = reinterpret_cast<const float4*>(rbuf)[t];
            float* dst;
            if (t < F2ITEMS) {
                const int xcol = t % XCOLS;
                const int row  = t / XCOLS;
                dst = tb + (row * CC) * ROWLEN + swzidx(xcol);
            } else {
                const int u  = t - F2ITEMS;
                const int x  = u & (DW - 1);
                const int r2 = u >> 8;
                dst = tF1 + (r2 * CC) * ROWLEN + swzidx(x);
            }
            dst[0]          = v.x;
            dst[ROWLEN]     = v.y;
            dst[2 * ROWLEN] = v.z;
            dst[3 * ROWLEN] = v.w;
        }
    };

    // Fixed physical window offsets for this lane.
    const int pw0 = swzchunk4(2 * g + 0);
    const int pw1 = swzchunk4(2 * g + 1);
    const int pw2 = swzchunk4(2 * g + 2);
    const int pw3 = swzchunk4(2 * g + 3);

    float acc[NDX][PX];
    #pragma unroll
    for (int a = 0; a < NDX; ++a)
        #pragma unroll
        for (int b = 0; b < PX; ++b) acc[a][b] = 0.f;

    // ---- prologue: chunks 0 and 1 in flight; transpose chunk 0 ----
    issue_chunk(0, raw_u[0]);
    issue_chunk(1, raw_u[1]);
    asm volatile("cp.async.wait_group 1;\n" ::: "memory");   // chunk 0 landed
    transpose_chunk(rawbuf[0], tbuf[0]);
    __syncthreads();

    for (int k = 0; k < NCH; ++k) {
        if (k + 1 < NCH) {
            asm volatile("cp.async.wait_group 0;\n" ::: "memory");  // chunk k+1 landed
            transpose_chunk(rawbuf[(k + 1) & 1], tbuf[(k + 1) & 1]);
            if (k + 2 < NCH) issue_chunk(k + 2, raw_u[k & 1]);
        }
        // ---- compute chunk k: 4 channels x 72 FMAs, register-resident window ----
        const float* tb = tbuf[k & 1];
        const float* tF1 = tb + YROWS * CC * ROWLEN;
        #pragma unroll
        for (int c = 0; c < CC; ++c) {
            const float* r1 = tF1 + (r * CC + c) * ROWLEN;
            const float4 a0 = *reinterpret_cast<const float4*>(r1 + pw0);
            const float4 a1 = *reinterpret_cast<const float4*>(r1 + pw1);
            const float* r2 = tb + ((r + i) * CC + c) * ROWLEN;
            const float4 w0 = *reinterpret_cast<const float4*>(r2 + pw0);
            const float4 w1 = *reinterpret_cast<const float4*>(r2 + pw1);
            const float4 w2 = *reinterpret_cast<const float4*>(r2 + pw2);
            const float4 w3 = *reinterpret_cast<const float4*>(r2 + pw3);
            const float a[PX]  = {a0.x, a0.y, a0.z, a0.w, a1.x, a1.y, a1.z, a1.w};
            const float wv[16] = {w0.x, w0.y, w0.z, w0.w, w1.x, w1.y, w1.z, w1.w,
                                  w2.x, w2.y, w2.z, w2.w, w3.x, w3.y, w3.z, w3.w};
            #pragma unroll
            for (int dx = 0; dx < NDX; ++dx)
                #pragma unroll
                for (int p = 0; p < PX; ++p)
                    acc[dx][p] = fmaf(a[p], wv[p + dx], acc[dx][p]);
        }
        __syncthreads();
    }

    // ---- epilogue ----
    const float inv = 1.0f / (float)DC;
    const int pixBase = rowPix + r * DW + g * PX;
    #pragma unroll
    for (int p = 0; p < PX; ++p) {
        const int ob = (pixBase + p) * NOFF + i * NDX;
        #pragma unroll
        for (int dx = 0; dx < NDX; ++dx)
            out[ob + dx] = acc[dx][p] * inv;
    }
}

extern "C" void kernel_launch(void* const* d_in, const int* in_sizes, int n_in,
                              void* d_out, int out_size)
{
    const float* f1 = (const float*)d_in[0];
    const float* f2 = (const float*)d_in[1];
    float* out      = (float*)d_out;

    cudaFuncSetAttribute(costvol_kernel,
                         cudaFuncAttributeMaxDynamicSharedMemorySize, SMEM_BYTES);
    dim3 grid(DH / YB, DN);  // y fastest -> adjacent blocks share f2 halo in L2
    costvol_kernel<<<grid, THREADS, SMEM_BYTES>>>(f1, f2, out);
}

// round 7
// speedup vs baseline: 1.1151x; 1.1151x over previous
#include <cuda_runtime.h>

// cost_volumn: out[n,y,x, i*9+j] = (1/128) * sum_c f1[n,y,x,c] * f2[n, y+i-4, x+j-4, c]
// f1,f2: [8,128,256,128] f32 NHWC; out: [8,128,256,81] f32. Zero padding outside.
//
// Pixel-major dot4 design: cp.async lands 16B (=4 channels of one pixel) DIRECTLY
// into the swizzled compute buffer (no transpose, no STS). Compute does
// acc[dx][p] += dot4(a_quad[p], w_quad[p+dx]) on register-resident window quads.
// CC=8 channels/chunk (2 quad planes), double-buffered, 1 barrier per chunk.

#define DN 8
#define DH 128
#define DW 256
#define DC 128
#define RAD 4
#define NDX 9
#define NOFF 81

constexpr int YB      = 2;             // output rows per block
constexpr int CC      = 8;             // channels per chunk (2 float4 quads)
constexpr int NCH     = DC / CC;       // 16 chunks
constexpr int PX      = 8;             // pixels per thread
constexpr int THREADS = 576;           // 18 warps; warp=(row,dy), lane=x-group
constexpr int XCOLS   = DW + 2 * RAD;  // 264 f2 columns
constexpr int YROWS   = YB + 2 * RAD;  // 10 f2 rows

// Buffer geometry in 16B chunks: [f2 quad0 | f2 quad1 | f1 quad0 | f1 quad1]
constexpr int F2PLANE = YROWS * XCOLS;           // 2640 chunks per quad plane
constexpr int F1PLANE = YB * DW;                 // 512 chunks per quad plane
constexpr int BUFCHUNKS = 2 * F2PLANE + 2 * F1PLANE;   // 6304
constexpr int NBUF    = 2;
constexpr int SMEM_BYTES = NBUF * BUFCHUNKS * 16;      // 201,728 B

constexpr int F2ITEMS = 2 * F2PLANE;             // 5280 cp.async items (f2)
constexpr int TOTITEMS = BUFCHUNKS;              // 6304 items per chunk

// XOR swizzle on 16B-chunk index: quarter-warp-conflict-free for stride-8 windows.
__device__ __forceinline__ int swz(int x) {      // chunk idx -> physical chunk idx
    return (x & ~7) | ((x ^ (x >> 3)) & 7);
}

extern __shared__ float smem[];

__device__ __forceinline__ void cp16(unsigned dst, const void* src, int srcsize) {
    asm volatile("cp.async.cg.shared.global [%0], [%1], 16, %2;\n"
                 :: "r"(dst), "l"(src), "r"(srcsize));
}
__device__ __forceinline__ float dot4(float4 a, float4 b, float acc) {
    acc = fmaf(a.x, b.x, acc);
    acc = fmaf(a.y, b.y, acc);
    acc = fmaf(a.z, b.z, acc);
    acc = fmaf(a.w, b.w, acc);
    return acc;
}

__global__ __launch_bounds__(THREADS)
void costvol_kernel(const float* __restrict__ f1,
                    const float* __restrict__ f2,
                    float* __restrict__ out)
{
    const int y0  = blockIdx.x * YB;
    const int n   = blockIdx.y;
    const int tid = threadIdx.x;
    const int w   = tid >> 5;
    const int r   = w / NDX;           // output row in block (0..1)
    const int i   = w % NDX;           // dy 0..8
    const int g   = tid & 31;          // x-group: pixels 8g..8g+7

    const unsigned smem_u = (unsigned)__cvta_generic_to_shared(smem);
    const int rowPix = (n * DH + y0) * DW;

    // ---- cp.async one chunk (CC=8 channels) straight into swizzled buffer ----
    auto issue_chunk = [&](int ch, int buf) {
        const unsigned bbase = smem_u + (unsigned)buf * BUFCHUNKS * 16u;
        const int cofs = ch * CC;
        #pragma unroll 1
        for (int t = tid; t < TOTITEMS; t += THREADS) {
            const int q = t & 1;               // quad 0/1
            const int u = t >> 1;              // pixel-item
            const float* src;
            int sz, dstc;
            if (u < F2PLANE) {
                const int xcol = u % XCOLS;
                const int row  = u / XCOLS;
                const int y2 = y0 + row - RAD;
                const int x2 = xcol - RAD;
                const bool ok = ((unsigned)y2 < DH) & ((unsigned)x2 < DW);
                src = f2 + (size_t)((n * DH + (ok ? y2 : 0)) * DW + (ok ? x2 : 0)) * DC
                          + cofs + q * 4;
                sz  = ok ? 16 : 0;
                dstc = q * F2PLANE + row * XCOLS + swz(xcol);
            } else {
                const int v  = u - F2PLANE;    // 0..511
                const int x  = v & (DW - 1);
                const int r2 = v >> 8;
                src = f1 + (size_t)(rowPix + r2 * DW + x) * DC + cofs + q * 4;
                sz  = 16;
                dstc = 2 * F2PLANE + q * F1PLANE + r2 * DW + swz(x);
            }
            cp16(bbase + (unsigned)dstc * 16u, src, sz);
        }
        asm volatile("cp.async.commit_group;\n" ::: "memory");
    };

    float acc[NDX][PX];
    #pragma unroll
    for (int a = 0; a < NDX; ++a)
        #pragma unroll
        for (int b = 0; b < PX; ++b) acc[a][b] = 0.f;

    issue_chunk(0, 0);

    for (int k = 0; k < NCH; ++k) {
        asm volatile("cp.async.wait_group 0;\n" ::: "memory");  // chunk k landed (mine)
        __syncthreads();                                        // visible to all; buf free
        if (k + 1 < NCH) issue_chunk(k + 1, (k + 1) & 1);

        const float* buf = smem + (size_t)(k & 1) * BUFCHUNKS * 4;
        #pragma unroll
        for (int q = 0; q < 2; ++q) {
            const float* F1p = buf + (size_t)(2 * F2PLANE + q * F1PLANE + r * DW) * 4;
            const float* Wp  = buf + (size_t)(q * F2PLANE + (r + i) * XCOLS) * 4;
            #pragma unroll
            for (int h = 0; h < 2; ++h) {
                const int xb = 8 * g + 4 * h;   // first pixel of this half
                float4 a4[4];
                #pragma unroll
                for (int p = 0; p < 4; ++p)
                    a4[p] = *reinterpret_cast<const float4*>(F1p + swz(xb + p) * 4);
                #pragma unroll
                for (int kk = 0; kk < 12; ++kk) {
                    const float4 w4 = *reinterpret_cast<const float4*>(Wp + swz(xb + kk) * 4);
                    const int pmin = (kk - 8) > 0 ? (kk - 8) : 0;
                    const int pmax = kk < 3 ? kk : 3;
                    #pragma unroll
                    for (int p = 0; p < 4; ++p)
                        if (p >= pmin && p <= pmax)
                            acc[kk - p][4 * h + p] = dot4(a4[p], w4, acc[kk - p][4 * h + p]);
                }
            }
        }
    }

    // ---- epilogue ----
    const float inv = 1.0f / (float)DC;
    const int pixBase = rowPix + r * DW + g * PX;
    #pragma unroll
    for (int p = 0; p < PX; ++p) {
        const int ob = (pixBase + p) * NOFF + i * NDX;
        #pragma unroll
        for (int dx = 0; dx < NDX; ++dx)
            out[ob + dx] = acc[dx][p] * inv;
    }
}

extern "C" void kernel_launch(void* const* d_in, const int* in_sizes, int n_in,
                              void* d_out, int out_size)
{
    const float* f1 = (const float*)d_in[0];
    const float* f2 = (const float*)d_in[1];
    float* out      = (float*)d_out;

    cudaFuncSetAttribute(costvol_kernel,
                         cudaFuncAttributeMaxDynamicSharedMemorySize, SMEM_BYTES);
    dim3 grid(DH / YB, DN);  // y fastest -> adjacent blocks share f2 halo in L2
    costvol_kernel<<<grid, THREADS, SMEM_BYTES>>>(f1, f2, out);
}